// round 10
// baseline (speedup 1.0000x reference)
#include <cuda_runtime.h>
#include <math.h>
#include <stdint.h>

#define DI __device__ __forceinline__

#define BB 256
#define THc 512
#define TAc 576

// output section offsets (floats): y, prior_m, prior_s, qm_all, qs_all, h_seq
#define OFF_PM ((size_t)131072)
#define OFF_PS ((size_t)16908288)
#define OFF_QM ((size_t)33685504)
#define OFF_QS ((size_t)52559872)
#define OFF_HS ((size_t)71434240)

// ---------------- scratch ----------------
__device__ float g_xgf[(size_t)BB * TAc * 1024];
__device__ float g_xgb[(size_t)BB * TAc * 1024];
__device__ float g_xgg[(size_t)BB * THc * 1536];
__device__ float g_hbi[(size_t)BB * TAc * 512];
__device__ float g_z[(size_t)BB * THc * 128];
__device__ float g_hst[2][2][65536];   // [dir][parity][b*256+h]  ping-pong (race-free)
__device__ float g_hg[2][131072];      // [parity][b*512+h]
__device__ float g_cst[2 * 65536];     // cell state (exclusive per thread)
__device__ float g_Wf[16 * 1024], g_Wb[16 * 1024], g_Wg[16 * 1536];
__device__ float g_bf[1024], g_bb[1024], g_bg[1536];
__device__ float g_Weh[512];
__device__ float g_yb[1];

// ---------------- helpers ----------------
DI float to_tf32(float x) { unsigned u; asm("cvt.rna.tf32.f32 %0, %1;" : "=r"(u) : "f"(x)); return __uint_as_float(u); }
DI unsigned fau(float x) { return __float_as_uint(x); }
DI void mma8(float* c, const unsigned* a, const unsigned* b) {
    asm volatile("mma.sync.aligned.m16n8k8.row.col.f32.tf32.tf32.f32 "
                 "{%0,%1,%2,%3},{%4,%5,%6,%7},{%8,%9},{%0,%1,%2,%3};\n"
                 : "+f"(c[0]), "+f"(c[1]), "+f"(c[2]), "+f"(c[3])
                 : "r"(a[0]), "r"(a[1]), "r"(a[2]), "r"(a[3]), "r"(b[0]), "r"(b[1]));
}
DI float sigf(float x) { return 1.f / (1.f + expf(-x)); }
DI float splus(float x) { return (x > 20.f ? x : log1pf(expf(x))) + 1e-5f; }
DI float geluf(float x) { return 0.5f * x * (1.f + erff(x * 0.70710678f)); }

// ---------------- weight folding ----------------
__global__ __launch_bounds__(256) void k_fuse(
    const float* We, const float* be,
    const float* Wihf, const float* bihf, const float* Wihb, const float* bihb,
    const float* Wihg, const float* bihg,
    const float* We2, const float* be2, const float* Whead, const float* bhead)
{
    int o = blockIdx.x * 256 + threadIdx.x;
    if (o < 16384) { int p = o >> 10, n = o & 1023; float a = 0.f;
        for (int d = 0; d < 512; d++) a += We[p * 512 + d] * Wihf[d * 1024 + n];
        g_Wf[o] = a; return; }
    o -= 16384;
    if (o < 16384) { int p = o >> 10, n = o & 1023; float a = 0.f;
        for (int d = 0; d < 512; d++) a += We[p * 512 + d] * Wihb[d * 1024 + n];
        g_Wb[o] = a; return; }
    o -= 16384;
    if (o < 24576) { int p = o / 1536, n = o - p * 1536; float a = 0.f;
        for (int d = 0; d < 512; d++) a += We[p * 512 + d] * Wihg[d * 1536 + n];
        g_Wg[o] = a; return; }
    o -= 24576;
    if (o < 1024) { float a = bihf[o];
        for (int d = 0; d < 512; d++) a += be[d] * Wihf[d * 1024 + o];
        g_bf[o] = a; return; }
    o -= 1024;
    if (o < 1024) { float a = bihb[o];
        for (int d = 0; d < 512; d++) a += be[d] * Wihb[d * 1024 + o];
        g_bb[o] = a; return; }
    o -= 1024;
    if (o < 1536) { float a = bihg[o];
        for (int d = 0; d < 512; d++) a += be[d] * Wihg[d * 1536 + o];
        g_bg[o] = a; return; }
    o -= 1536;
    if (o < 512) { float a = 0.f;
        for (int j = 0; j < 512; j++) a += We2[o * 512 + j] * Whead[j];
        g_Weh[o] = a; return; }
    o -= 512;
    if (o == 0) { float a = bhead[0];
        for (int j = 0; j < 512; j++) a += be2[j] * Whead[j];
        g_yb[0] = a; }
}

__global__ __launch_bounds__(256) void k_init(float* Y)
{
    int i = blockIdx.x * 256 + threadIdx.x;
    if (i < 131072) {
        Y[i] = g_yb[0];
        g_cst[i] = 0.f;
        g_hg[0][i] = 0.f;
        if (i < 65536) { g_hst[0][0][i] = 0.f; g_hst[1][0][i] = 0.f; }
    }
}

// ---------------- input-gate GEMM, K=16 (fused embed) ----------------
__global__ __launch_bounds__(256) void k_xg(
    const float* __restrict__ A, const float* __restrict__ W,
    const float* __restrict__ bias, float* __restrict__ C, int M, int N)
{
    int nq = N >> 2;
    long long i = (long long)blockIdx.x * 256 + threadIdx.x;
    int r = (int)(i / nq), q = (int)(i - (long long)r * nq);
    if (r >= M) return;
    float av[16];
    const float4* ap = (const float4*)(A + (size_t)r * 16);
#pragma unroll
    for (int j = 0; j < 4; j++) { float4 v = ap[j]; av[j*4]=v.x; av[j*4+1]=v.y; av[j*4+2]=v.z; av[j*4+3]=v.w; }
    float4 acc = *(const float4*)(bias + q * 4);
#pragma unroll
    for (int p = 0; p < 16; p++) {
        float4 w = *(const float4*)(W + (size_t)p * N + q * 4);
        acc.x += av[p] * w.x; acc.y += av[p] * w.y; acc.z += av[p] * w.z; acc.w += av[p] * w.w;
    }
    *(float4*)(C + (size_t)r * N + q * 4) = acc;
}

// ---------------- recurrence GEMM core (gate-aligned tiles) ----------------
template <int NG>
DI void rec_gemm(float (&acc)[2][2][NG][4], float (*As)[20], float (*Bs)[264],
                 const float* hst, const float* W, int ldw, int K, int gstride,
                 int b0, int colbase, int tid, int wm, int wn, int gq, int tq)
{
    float4 va; float4 vb[NG];
    int r = tid >> 2, q = (tid & 3) * 4;
    int r2 = tid >> 4, qq = tid & 15;
    auto ld = [&](int kc) {
        va = *(const float4*)(hst + (size_t)(b0 + r) * K + kc * 16 + q);
#pragma unroll
        for (int qi = 0; qi < NG; qi++) {
            int c4 = qq + qi * 16; int g = c4 >> 4; int jj = (c4 & 15) * 4;
            vb[qi] = *(const float4*)(W + (size_t)(kc * 16 + r2) * ldw + g * gstride + colbase + jj);
        }
    };
    auto st = [&]() {
        As[r][q] = to_tf32(va.x); As[r][q+1] = to_tf32(va.y); As[r][q+2] = to_tf32(va.z); As[r][q+3] = to_tf32(va.w);
#pragma unroll
        for (int qi = 0; qi < NG; qi++) {
            int c4 = qq + qi * 16; float* p = &Bs[r2][c4 * 4];
            p[0] = to_tf32(vb[qi].x); p[1] = to_tf32(vb[qi].y); p[2] = to_tf32(vb[qi].z); p[3] = to_tf32(vb[qi].w);
        }
    };
    ld(0); st(); __syncthreads();
    int NC = K >> 4;
    for (int kc = 0; kc < NC; kc++) {
        if (kc + 1 < NC) ld(kc + 1);
#pragma unroll
        for (int kk = 0; kk < 2; kk++) {
            int kb = kk * 8; unsigned a[2][4];
#pragma unroll
            for (int m = 0; m < 2; m++) {
                int rb = wm * 32 + m * 16;
                a[m][0] = fau(As[rb + gq][kb + tq]);     a[m][1] = fau(As[rb + gq + 8][kb + tq]);
                a[m][2] = fau(As[rb + gq][kb + tq + 4]); a[m][3] = fau(As[rb + gq + 8][kb + tq + 4]);
            }
#pragma unroll
            for (int g = 0; g < NG; g++)
#pragma unroll
            for (int nn = 0; nn < 2; nn++) {
                int pc = g * 64 + wn * 16 + nn * 8 + gq;
                unsigned bv[2] = { fau(Bs[kb + tq][pc]), fau(Bs[kb + tq + 4][pc]) };
                mma8(acc[0][nn][g], a[0], bv); mma8(acc[1][nn][g], a[1], bv);
            }
        }
        __syncthreads();
        if (kc + 1 < NC) { st(); __syncthreads(); }
    }
}

// ---------------- combined step: LSTM fwd/bwd + GRU ----------------
__global__ __launch_bounds__(256) void k_step(int s,
    const float* __restrict__ Whf, const float* __restrict__ bhf,
    const float* __restrict__ Whb, const float* __restrict__ bhb,
    const float* __restrict__ Whg, const float* __restrict__ bhg,
    float* __restrict__ out)
{
    __shared__ float As[64][20];
    __shared__ float Bs[16][264];
    int z = blockIdx.z, bx = blockIdx.x, by = blockIdx.y;
    int tid = threadIdx.x, wid = tid >> 5, lane = tid & 31, gq = lane >> 2, tq = lane & 3;
    int wm = wid >> 2, wn = wid & 3;
    int b0 = bx * 64;
    int pr = s & 1, pw = pr ^ 1;
    if (z < 2) {
        if (by >= 4) return;
        int t = z ? 575 - s : s;
        const float* Whh = z ? Whb : Whf;
        const float* bhh = z ? bhb : bhf;
        const float* hrd = g_hst[z][pr];
        float* hwr = g_hst[z][pw];
        float* cst = g_cst + z * 65536;
        const float* xg = z ? g_xgb : g_xgf;
        float acc[2][2][4][4];
#pragma unroll
        for (int m = 0; m < 2; m++) for (int nn = 0; nn < 2; nn++)
            for (int g = 0; g < 4; g++) for (int j = 0; j < 4; j++) acc[m][nn][g][j] = 0.f;
        rec_gemm<4>(acc, As, Bs, hrd, Whh, 1024, 256, 256, b0, by * 64, tid, wm, wn, gq, tq);
#pragma unroll
        for (int m = 0; m < 2; m++)
#pragma unroll
        for (int nn = 0; nn < 2; nn++)
#pragma unroll
        for (int half = 0; half < 2; half++) {
            int ci = half * 2;
            int r = b0 + wm * 32 + m * 16 + gq + half * 8;
            int hcol = by * 64 + wn * 16 + nn * 8 + 2 * tq;
            size_t xb = ((size_t)r * TAc + t) * 1024;
            float gv[4][2];
#pragma unroll
            for (int g = 0; g < 4; g++) {
                int c = g * 256 + hcol;
                gv[g][0] = acc[m][nn][g][ci]     + xg[xb + c]     + bhh[c];
                gv[g][1] = acc[m][nn][g][ci + 1] + xg[xb + c + 1] + bhh[c + 1];
            }
            size_t si = (size_t)r * 256 + hcol;
            size_t oi = ((size_t)r * TAc + t) * 512 + z * 256 + hcol;
#pragma unroll
            for (int j = 0; j < 2; j++) {
                float cn = sigf(gv[1][j]) * cst[si + j] + sigf(gv[0][j]) * tanhf(gv[2][j]);
                float hv = sigf(gv[3][j]) * tanhf(cn);
                cst[si + j] = cn; hwr[si + j] = hv;
                g_hbi[oi + j] = hv;
            }
        }
    } else {
        if (s >= 512) return;
        int t = s;
        const float* xg = g_xgg;
        const float* ghr = g_hg[pr];
        float* ghw = g_hg[pw];
        float acc[2][2][3][4];
#pragma unroll
        for (int m = 0; m < 2; m++) for (int nn = 0; nn < 2; nn++)
            for (int g = 0; g < 3; g++) for (int j = 0; j < 4; j++) acc[m][nn][g][j] = 0.f;
        rec_gemm<3>(acc, As, Bs, ghr, Whg, 1536, 512, 512, b0, by * 64, tid, wm, wn, gq, tq);
#pragma unroll
        for (int m = 0; m < 2; m++)
#pragma unroll
        for (int nn = 0; nn < 2; nn++)
#pragma unroll
        for (int half = 0; half < 2; half++) {
            int ci = half * 2;
            int r = b0 + wm * 32 + m * 16 + gq + half * 8;
            int hcol = by * 64 + wn * 16 + nn * 8 + 2 * tq;
            size_t xb = ((size_t)r * THc + t) * 1536;
            size_t si = (size_t)r * 512 + hcol;
            size_t oi = OFF_HS + ((size_t)r * THc + t) * 512 + hcol;
#pragma unroll
            for (int j = 0; j < 2; j++) {
                float hr = acc[m][nn][0][ci + j] + bhg[hcol + j];
                float hz = acc[m][nn][1][ci + j] + bhg[512 + hcol + j];
                float hn = acc[m][nn][2][ci + j] + bhg[1024 + hcol + j];
                float rv = sigf(xg[xb + hcol + j] + hr);
                float zv = sigf(xg[xb + 512 + hcol + j] + hz);
                float nv = tanhf(xg[xb + 1024 + hcol + j] + rv * hn);
                float hv = (1.f - zv) * nv + zv * ghr[si + j];
                ghw[si + j] = hv;
                out[oi + j] = hv;
            }
        }
    }
}

// ---------------- generic tf32 GEMM 64x128x16 tiles ----------------
template <int EPI, int CAT>
__global__ __launch_bounds__(256) void k_gemm(
    const float* __restrict__ A, const float* __restrict__ Az,
    const float* __restrict__ W, const float* __restrict__ bias,
    float* __restrict__ C, float* __restrict__ Y, int M, int N, int K)
{
    __shared__ float As[64 * 20];
    __shared__ float Ws[16 * 136];
    const int tid = threadIdx.x, wid = tid >> 5, lane = tid & 31;
    const int gq = lane >> 2, tq = lane & 3;
    const int wm = wid >> 1, wn = wid & 1;
    const int r0 = blockIdx.x * 64, n0 = blockIdx.y * 128;
    const int ar = tid >> 2, aq = tid & 3;
    const int bk = tid >> 5, bc = tid & 31;
    const int ldA = CAT ? 512 : K;

    float acc[8][4];
#pragma unroll
    for (int i = 0; i < 8; i++) for (int q = 0; q < 4; q++) acc[i][q] = 0.f;

    float4 ra, rb0, rb1;
    const int NC = K >> 4;
    auto lda = [&](int kc) {
        int k = kc * 16 + aq * 4;
        const float* p = (CAT && k >= 512) ? (Az + (size_t)(r0 + ar) * 128 + (k - 512))
                                           : (A + (size_t)(r0 + ar) * ldA + k);
        ra = *(const float4*)p;
    };
    auto ldb = [&](int kc) {
        rb0 = *(const float4*)(W + (size_t)(kc * 16 + bk) * N + n0 + bc * 4);
        rb1 = *(const float4*)(W + (size_t)(kc * 16 + bk + 8) * N + n0 + bc * 4);
    };
    auto st = [&]() {
        float* pa = &As[ar * 20 + aq * 4];
        pa[0] = to_tf32(ra.x); pa[1] = to_tf32(ra.y); pa[2] = to_tf32(ra.z); pa[3] = to_tf32(ra.w);
        float* pb = &Ws[bk * 136 + bc * 4];
        pb[0] = to_tf32(rb0.x); pb[1] = to_tf32(rb0.y); pb[2] = to_tf32(rb0.z); pb[3] = to_tf32(rb0.w);
        float* pb2 = &Ws[(bk + 8) * 136 + bc * 4];
        pb2[0] = to_tf32(rb1.x); pb2[1] = to_tf32(rb1.y); pb2[2] = to_tf32(rb1.z); pb2[3] = to_tf32(rb1.w);
    };
    lda(0); ldb(0); st(); __syncthreads();
    for (int kc = 0; kc < NC; kc++) {
        if (kc + 1 < NC) { lda(kc + 1); ldb(kc + 1); }
#pragma unroll
        for (int kk = 0; kk < 2; kk++) {
            unsigned a[4];
            const int kb = kk * 8, rowb = wm * 16;
            a[0] = fau(As[(rowb + gq) * 20 + kb + tq]);
            a[1] = fau(As[(rowb + gq + 8) * 20 + kb + tq]);
            a[2] = fau(As[(rowb + gq) * 20 + kb + tq + 4]);
            a[3] = fau(As[(rowb + gq + 8) * 20 + kb + tq + 4]);
#pragma unroll
            for (int nf = 0; nf < 8; nf++) {
                const int nb = wn * 64 + nf * 8;
                unsigned bv[2] = { fau(Ws[(kb + tq) * 136 + nb + gq]),
                                   fau(Ws[(kb + tq + 4) * 136 + nb + gq]) };
                mma8(acc[nf], a, bv);
            }
        }
        __syncthreads();
        if (kc + 1 < NC) { st(); __syncthreads(); }
    }
    const int row = r0 + wm * 16 + gq;
    if (EPI == 2) {
        float p0 = 0.f, p1 = 0.f;
#pragma unroll
        for (int nf = 0; nf < 8; nf++) {
            const int colb = n0 + wn * 64 + nf * 8 + 2 * tq;
            const float b0v = bias[colb], b1v = bias[colb + 1];
            float v0 = geluf(acc[nf][0] + b0v), v1 = geluf(acc[nf][1] + b1v);
            float v2 = geluf(acc[nf][2] + b0v), v3 = geluf(acc[nf][3] + b1v);
            p0 += v0 * g_Weh[colb] + v1 * g_Weh[colb + 1];
            p1 += v2 * g_Weh[colb] + v3 * g_Weh[colb + 1];
        }
        p0 += __shfl_xor_sync(0xffffffffu, p0, 1); p0 += __shfl_xor_sync(0xffffffffu, p0, 2);
        p1 += __shfl_xor_sync(0xffffffffu, p1, 1); p1 += __shfl_xor_sync(0xffffffffu, p1, 2);
        if (tq == 0) { atomicAdd(Y + row, p0); atomicAdd(Y + row + 8, p1); }
    } else {
#pragma unroll
        for (int nf = 0; nf < 8; nf++) {
            const int colb = n0 + wn * 64 + nf * 8 + 2 * tq;
            const float b0v = bias[colb], b1v = bias[colb + 1];
            float v0 = acc[nf][0] + b0v, v1 = acc[nf][1] + b1v;
            float v2 = acc[nf][2] + b0v, v3 = acc[nf][3] + b1v;
            if (EPI == 1) { v0 = splus(v0); v1 = splus(v1); v2 = splus(v2); v3 = splus(v3); }
            *(float2*)(C + (size_t)row * N + colb) = make_float2(v0, v1);
            *(float2*)(C + (size_t)(row + 8) * N + colb) = make_float2(v2, v3);
        }
    }
}

// ---------------- reparam sample ----------------
__global__ __launch_bounds__(256) void k_z(const float* __restrict__ out, const float* __restrict__ eps)
{
    int i = blockIdx.x * 256 + threadIdx.x;   // < 16777216
    int b = i >> 16, rem = i & 65535;
    int t = rem >> 7, l = rem & 127;
    size_t qi = ((size_t)b * TAc + t) * 128 + l;
    g_z[i] = out[OFF_QM + qi] + out[OFF_QS + qi] * eps[i];
}

// ---------------- host ----------------
extern "C" void kernel_launch(void* const* d_in, const int* in_sizes, int n_in,
                              void* d_out, int out_size)
{
    const float* ph   = (const float*)d_in[0];
    const float* pa   = (const float*)d_in[1];
    const float* eps  = (const float*)d_in[2];
    const float* We   = (const float*)d_in[3];
    const float* be   = (const float*)d_in[4];
    const float* Wihf = (const float*)d_in[5];
    const float* Whhf = (const float*)d_in[6];
    const float* bihf = (const float*)d_in[7];
    const float* bhhf = (const float*)d_in[8];
    const float* Wihb = (const float*)d_in[9];
    const float* Whhb = (const float*)d_in[10];
    const float* bihb = (const float*)d_in[11];
    const float* bhhb = (const float*)d_in[12];
    const float* Wqm  = (const float*)d_in[13];
    const float* bqm  = (const float*)d_in[14];
    const float* Wqs  = (const float*)d_in[15];
    const float* bqs  = (const float*)d_in[16];
    const float* Wihg = (const float*)d_in[17];
    const float* Whhg = (const float*)d_in[18];
    const float* bihg = (const float*)d_in[19];
    const float* bhhg = (const float*)d_in[20];
    const float* Wpm  = (const float*)d_in[21];
    const float* bpm  = (const float*)d_in[22];
    const float* Wps  = (const float*)d_in[23];
    const float* bps  = (const float*)d_in[24];
    const float* We1  = (const float*)d_in[25];
    const float* be1  = (const float*)d_in[26];
    const float* We2  = (const float*)d_in[27];
    const float* be2  = (const float*)d_in[28];
    const float* Whead= (const float*)d_in[29];
    const float* bhead= (const float*)d_in[30];
    float* out = (float*)d_out;

    float *xgf, *xgb, *xgg, *hbi, *zb, *Wf, *Wb, *Wg, *bf, *bb, *bg;
    cudaGetSymbolAddress((void**)&xgf, g_xgf);
    cudaGetSymbolAddress((void**)&xgb, g_xgb);
    cudaGetSymbolAddress((void**)&xgg, g_xgg);
    cudaGetSymbolAddress((void**)&hbi, g_hbi);
    cudaGetSymbolAddress((void**)&zb,  g_z);
    cudaGetSymbolAddress((void**)&Wf,  g_Wf);
    cudaGetSymbolAddress((void**)&Wb,  g_Wb);
    cudaGetSymbolAddress((void**)&Wg,  g_Wg);
    cudaGetSymbolAddress((void**)&bf,  g_bf);
    cudaGetSymbolAddress((void**)&bb,  g_bb);
    cudaGetSymbolAddress((void**)&bg,  g_bg);

    k_fuse<<<256, 256>>>(We, be, Wihf, bihf, Wihb, bihb, Wihg, bihg, We2, be2, Whead, bhead);
    k_init<<<512, 256>>>(out);

    // input gates (fused embedding), K=16
    k_xg<<<147456, 256>>>(pa, Wf, bf, xgf, BB * TAc, 1024);
    k_xg<<<147456, 256>>>(pa, Wb, bb, xgb, BB * TAc, 1024);
    k_xg<<<196608, 256>>>(ph, Wg, bg, xgg, BB * THc, 1536);

    // recurrences (576 steps; LSTM fwd/bwd + GRU fused per launch)
    for (int s = 0; s < 576; s++)
        k_step<<<dim3(4, 8, 3), 256>>>(s, Whhf, bhhf, Whhb, bhhb, Whhg, bhhg, out);

    // heads
    k_gemm<0, 0><<<dim3(2304, 1), 256>>>(hbi, nullptr, Wqm, bqm, out + OFF_QM, nullptr, BB * TAc, 128, 512);
    k_gemm<1, 0><<<dim3(2304, 1), 256>>>(hbi, nullptr, Wqs, bqs, out + OFF_QS, nullptr, BB * TAc, 128, 512);
    k_gemm<0, 0><<<dim3(2048, 1), 256>>>(out + OFF_HS, nullptr, Wpm, bpm, out + OFF_PM, nullptr, BB * THc, 128, 512);
    k_gemm<1, 0><<<dim3(2048, 1), 256>>>(out + OFF_HS, nullptr, Wps, bps, out + OFF_PS, nullptr, BB * THc, 128, 512);

    // reparam + emission (gelu GEMM fused with folded head dot)
    k_z<<<65536, 256>>>(out, eps);
    k_gemm<2, 1><<<dim3(2048, 4), 256>>>(out + OFF_HS, zb, We1, be1, nullptr, out, BB * THc, 512, 640);
}

// round 12
// speedup vs baseline: 1.0960x; 1.0960x over previous
#include <cuda_runtime.h>
#include <math.h>
#include <stdint.h>

#define DI __device__ __forceinline__

#define BB 256
#define THc 512
#define TAc 576

// output section offsets (floats): y, prior_m, prior_s, qm_all, qs_all, h_seq
#define OFF_PM ((size_t)131072)
#define OFF_PS ((size_t)16908288)
#define OFF_QM ((size_t)33685504)
#define OFF_QS ((size_t)52559872)
#define OFF_HS ((size_t)71434240)

// ---------------- scratch ----------------
__device__ float g_xgf[(size_t)BB * TAc * 1024];
__device__ float g_xgb[(size_t)BB * TAc * 1024];
__device__ float g_xgg[(size_t)BB * THc * 1536];
__device__ float g_hbi[(size_t)BB * TAc * 512];
__device__ float g_z[(size_t)BB * THc * 128];
__device__ float g_hst[2][2][65536];   // [dir][parity][b*256+h]  ping-pong (race-free)
__device__ float g_hg[2][131072];      // [parity][b*512+h]
__device__ float g_cst[2 * 65536];     // cell state (exclusive per thread)
__device__ float g_Wf[16 * 1024], g_Wb[16 * 1024], g_Wg[16 * 1536];
__device__ float g_bf[1024], g_bb[1024], g_bg[1536];
__device__ float g_Weh[512];
__device__ float g_yb[1];

// ---------------- helpers ----------------
DI float to_tf32(float x) { unsigned u; asm("cvt.rna.tf32.f32 %0, %1;" : "=r"(u) : "f"(x)); return __uint_as_float(u); }
DI unsigned fau(float x) { return __float_as_uint(x); }
DI void mma8(float* c, const unsigned* a, const unsigned* b) {
    asm volatile("mma.sync.aligned.m16n8k8.row.col.f32.tf32.tf32.f32 "
                 "{%0,%1,%2,%3},{%4,%5,%6,%7},{%8,%9},{%0,%1,%2,%3};\n"
                 : "+f"(c[0]), "+f"(c[1]), "+f"(c[2]), "+f"(c[3])
                 : "r"(a[0]), "r"(a[1]), "r"(a[2]), "r"(a[3]), "r"(b[0]), "r"(b[1]));
}
DI float sigf(float x) { return 1.f / (1.f + expf(-x)); }
DI float splus(float x) { return (x > 20.f ? x : log1pf(expf(x))) + 1e-5f; }
DI float geluf(float x) { return 0.5f * x * (1.f + erff(x * 0.70710678f)); }

// ---------------- weight folding ----------------
__global__ __launch_bounds__(256) void k_fuse(
    const float* We, const float* be,
    const float* Wihf, const float* bihf, const float* Wihb, const float* bihb,
    const float* Wihg, const float* bihg,
    const float* We2, const float* be2, const float* Whead, const float* bhead)
{
    int o = blockIdx.x * 256 + threadIdx.x;
    if (o < 16384) { int p = o >> 10, n = o & 1023; float a = 0.f;
        for (int d = 0; d < 512; d++) a += We[p * 512 + d] * Wihf[d * 1024 + n];
        g_Wf[o] = a; return; }
    o -= 16384;
    if (o < 16384) { int p = o >> 10, n = o & 1023; float a = 0.f;
        for (int d = 0; d < 512; d++) a += We[p * 512 + d] * Wihb[d * 1024 + n];
        g_Wb[o] = a; return; }
    o -= 16384;
    if (o < 24576) { int p = o / 1536, n = o - p * 1536; float a = 0.f;
        for (int d = 0; d < 512; d++) a += We[p * 512 + d] * Wihg[d * 1536 + n];
        g_Wg[o] = a; return; }
    o -= 24576;
    if (o < 1024) { float a = bihf[o];
        for (int d = 0; d < 512; d++) a += be[d] * Wihf[d * 1024 + o];
        g_bf[o] = a; return; }
    o -= 1024;
    if (o < 1024) { float a = bihb[o];
        for (int d = 0; d < 512; d++) a += be[d] * Wihb[d * 1024 + o];
        g_bb[o] = a; return; }
    o -= 1024;
    if (o < 1536) { float a = bihg[o];
        for (int d = 0; d < 512; d++) a += be[d] * Wihg[d * 1536 + o];
        g_bg[o] = a; return; }
    o -= 1536;
    if (o < 512) { float a = 0.f;
        for (int j = 0; j < 512; j++) a += We2[o * 512 + j] * Whead[j];
        g_Weh[o] = a; return; }
    o -= 512;
    if (o == 0) { float a = bhead[0];
        for (int j = 0; j < 512; j++) a += be2[j] * Whead[j];
        g_yb[0] = a; }
}

__global__ __launch_bounds__(256) void k_init(float* Y)
{
    int i = blockIdx.x * 256 + threadIdx.x;
    if (i < 131072) {
        Y[i] = g_yb[0];
        g_cst[i] = 0.f;
        g_hg[0][i] = 0.f;
        if (i < 65536) { g_hst[0][0][i] = 0.f; g_hst[1][0][i] = 0.f; }
    }
}

// ---------------- input-gate GEMM, K=16 (fused embed) ----------------
__global__ __launch_bounds__(256) void k_xg(
    const float* __restrict__ A, const float* __restrict__ W,
    const float* __restrict__ bias, float* __restrict__ C, int M, int N)
{
    int nq = N >> 2;
    long long i = (long long)blockIdx.x * 256 + threadIdx.x;
    int r = (int)(i / nq), q = (int)(i - (long long)r * nq);
    if (r >= M) return;
    float av[16];
    const float4* ap = (const float4*)(A + (size_t)r * 16);
#pragma unroll
    for (int j = 0; j < 4; j++) { float4 v = ap[j]; av[j*4]=v.x; av[j*4+1]=v.y; av[j*4+2]=v.z; av[j*4+3]=v.w; }
    float4 acc = *(const float4*)(bias + q * 4);
#pragma unroll
    for (int p = 0; p < 16; p++) {
        float4 w = *(const float4*)(W + (size_t)p * N + q * 4);
        acc.x += av[p] * w.x; acc.y += av[p] * w.y; acc.z += av[p] * w.z; acc.w += av[p] * w.w;
    }
    *(float4*)(C + (size_t)r * N + q * 4) = acc;
}

// ---------------- recurrence GEMM core (32-row tiles, double-buffered) ----------------
template <int NG>
DI void rec_gemm(float (&acc)[2][NG][4], float (*As)[32][20], float (*Bs)[16][264],
                 const float* hst, const float* W, int ldw, int K, int gstride,
                 int b0, int colbase, int tid, int wm, int wn, int gq, int tq)
{
    float2 va; float4 vb[NG];
    int r = tid >> 3, q = (tid & 7) * 2;
    int r2 = tid >> 4, qq = tid & 15;
    auto ld = [&](int kc) {
        va = *(const float2*)(hst + (size_t)(b0 + r) * K + kc * 16 + q);
#pragma unroll
        for (int qi = 0; qi < NG; qi++) {
            int c4 = qq + qi * 16; int g = c4 >> 4; int jj = (c4 & 15) * 4;
            vb[qi] = *(const float4*)(W + (size_t)(kc * 16 + r2) * ldw + g * gstride + colbase + jj);
        }
    };
    auto st = [&](int bf) {
        As[bf][r][q] = to_tf32(va.x); As[bf][r][q + 1] = to_tf32(va.y);
#pragma unroll
        for (int qi = 0; qi < NG; qi++) {
            int c4 = qq + qi * 16; float* p = &Bs[bf][r2][c4 * 4];
            p[0] = to_tf32(vb[qi].x); p[1] = to_tf32(vb[qi].y); p[2] = to_tf32(vb[qi].z); p[3] = to_tf32(vb[qi].w);
        }
    };
    ld(0); st(0); __syncthreads();
    int NC = K >> 4;
    for (int kc = 0; kc < NC; kc++) {
        int cur = kc & 1;
        if (kc + 1 < NC) ld(kc + 1);
#pragma unroll
        for (int kk = 0; kk < 2; kk++) {
            int kb = kk * 8; unsigned a[4];
            int rb = wm * 16;
            a[0] = fau(As[cur][rb + gq][kb + tq]);     a[1] = fau(As[cur][rb + gq + 8][kb + tq]);
            a[2] = fau(As[cur][rb + gq][kb + tq + 4]); a[3] = fau(As[cur][rb + gq + 8][kb + tq + 4]);
#pragma unroll
            for (int g = 0; g < NG; g++)
#pragma unroll
            for (int nn = 0; nn < 2; nn++) {
                int pc = g * 64 + wn * 16 + nn * 8 + gq;
                unsigned bv[2] = { fau(Bs[cur][kb + tq][pc]), fau(Bs[cur][kb + tq + 4][pc]) };
                mma8(acc[nn][g], a, bv);
            }
        }
        if (kc + 1 < NC) st(cur ^ 1);
        __syncthreads();
    }
}

// ---------------- combined step: LSTM fwd/bwd + GRU ----------------
__global__ __launch_bounds__(256) void k_step(int s,
    const float* __restrict__ Whf, const float* __restrict__ bhf,
    const float* __restrict__ Whb, const float* __restrict__ bhb,
    const float* __restrict__ Whg, const float* __restrict__ bhg,
    float* __restrict__ out)
{
    __shared__ float As[2][32][20];
    __shared__ float Bs[2][16][264];
    int z = blockIdx.z, bx = blockIdx.x, by = blockIdx.y;
    int tid = threadIdx.x, wid = tid >> 5, lane = tid & 31, gq = lane >> 2, tq = lane & 3;
    int wm = wid >> 2, wn = wid & 3;
    int b0 = bx * 32;
    int pr = s & 1, pw = pr ^ 1;
    if (z < 2) {
        if (by >= 4) return;
        int t = z ? 575 - s : s;
        const float* Whh = z ? Whb : Whf;
        const float* bhh = z ? bhb : bhf;
        const float* hrd = g_hst[z][pr];
        float* hwr = g_hst[z][pw];
        float* cst = g_cst + z * 65536;
        const float* xg = z ? g_xgb : g_xgf;
        float acc[2][4][4];
#pragma unroll
        for (int nn = 0; nn < 2; nn++)
            for (int g = 0; g < 4; g++) for (int j = 0; j < 4; j++) acc[nn][g][j] = 0.f;
        rec_gemm<4>(acc, As, Bs, hrd, Whh, 1024, 256, 256, b0, by * 64, tid, wm, wn, gq, tq);
#pragma unroll
        for (int nn = 0; nn < 2; nn++)
#pragma unroll
        for (int half = 0; half < 2; half++) {
            int ci = half * 2;
            int r = b0 + wm * 16 + gq + half * 8;
            int hcol = by * 64 + wn * 16 + nn * 8 + 2 * tq;
            size_t xb = ((size_t)r * TAc + t) * 1024;
            float gv[4][2];
#pragma unroll
            for (int g = 0; g < 4; g++) {
                int c = g * 256 + hcol;
                gv[g][0] = acc[nn][g][ci]     + xg[xb + c]     + bhh[c];
                gv[g][1] = acc[nn][g][ci + 1] + xg[xb + c + 1] + bhh[c + 1];
            }
            size_t si = (size_t)r * 256 + hcol;
            size_t oi = ((size_t)r * TAc + t) * 512 + z * 256 + hcol;
#pragma unroll
            for (int j = 0; j < 2; j++) {
                float cn = sigf(gv[1][j]) * cst[si + j] + sigf(gv[0][j]) * tanhf(gv[2][j]);
                float hv = sigf(gv[3][j]) * tanhf(cn);
                cst[si + j] = cn; hwr[si + j] = hv;
                g_hbi[oi + j] = hv;
            }
        }
    } else {
        if (s >= 512) return;
        int t = s;
        const float* xg = g_xgg;
        const float* ghr = g_hg[pr];
        float* ghw = g_hg[pw];
        float acc[2][3][4];
#pragma unroll
        for (int nn = 0; nn < 2; nn++)
            for (int g = 0; g < 3; g++) for (int j = 0; j < 4; j++) acc[nn][g][j] = 0.f;
        rec_gemm<3>(acc, As, Bs, ghr, Whg, 1536, 512, 512, b0, by * 64, tid, wm, wn, gq, tq);
#pragma unroll
        for (int nn = 0; nn < 2; nn++)
#pragma unroll
        for (int half = 0; half < 2; half++) {
            int ci = half * 2;
            int r = b0 + wm * 16 + gq + half * 8;
            int hcol = by * 64 + wn * 16 + nn * 8 + 2 * tq;
            size_t xb = ((size_t)r * THc + t) * 1536;
            size_t si = (size_t)r * 512 + hcol;
            size_t oi = OFF_HS + ((size_t)r * THc + t) * 512 + hcol;
#pragma unroll
            for (int j = 0; j < 2; j++) {
                float hr = acc[nn][0][ci + j] + bhg[hcol + j];
                float hz = acc[nn][1][ci + j] + bhg[512 + hcol + j];
                float hn = acc[nn][2][ci + j] + bhg[1024 + hcol + j];
                float rv = sigf(xg[xb + hcol + j] + hr);
                float zv = sigf(xg[xb + 512 + hcol + j] + hz);
                float nv = tanhf(xg[xb + 1024 + hcol + j] + rv * hn);
                float hv = (1.f - zv) * nv + zv * ghr[si + j];
                ghw[si + j] = hv;
                out[oi + j] = hv;
            }
        }
    }
}

// ---------------- generic tf32 GEMM 64x128x16 tiles, double-buffered ----------------
template <int EPI, int CAT>
__global__ __launch_bounds__(256) void k_gemm(
    const float* __restrict__ A, const float* __restrict__ Az,
    const float* __restrict__ W, const float* __restrict__ bias,
    float* __restrict__ C, float* __restrict__ Y, int M, int N, int K)
{
    __shared__ float As[2][64 * 20];
    __shared__ float Ws[2][16 * 136];
    const int tid = threadIdx.x, wid = tid >> 5, lane = tid & 31;
    const int gq = lane >> 2, tq = lane & 3;
    const int wm = wid >> 1, wn = wid & 1;
    const int r0 = blockIdx.x * 64, n0 = blockIdx.y * 128;
    const int ar = tid >> 2, aq = tid & 3;
    const int bk = tid >> 5, bc = tid & 31;
    const int ldA = CAT ? 512 : K;

    float acc[8][4];
#pragma unroll
    for (int i = 0; i < 8; i++) for (int q = 0; q < 4; q++) acc[i][q] = 0.f;

    float4 ra, rb0, rb1;
    const int NC = K >> 4;
    auto lda = [&](int kc) {
        int k = kc * 16 + aq * 4;
        const float* p = (CAT && k >= 512) ? (Az + (size_t)(r0 + ar) * 128 + (k - 512))
                                           : (A + (size_t)(r0 + ar) * ldA + k);
        ra = *(const float4*)p;
    };
    auto ldb = [&](int kc) {
        rb0 = *(const float4*)(W + (size_t)(kc * 16 + bk) * N + n0 + bc * 4);
        rb1 = *(const float4*)(W + (size_t)(kc * 16 + bk + 8) * N + n0 + bc * 4);
    };
    auto st = [&](int bf) {
        float* pa = &As[bf][ar * 20 + aq * 4];
        pa[0] = to_tf32(ra.x); pa[1] = to_tf32(ra.y); pa[2] = to_tf32(ra.z); pa[3] = to_tf32(ra.w);
        float* pb = &Ws[bf][bk * 136 + bc * 4];
        pb[0] = to_tf32(rb0.x); pb[1] = to_tf32(rb0.y); pb[2] = to_tf32(rb0.z); pb[3] = to_tf32(rb0.w);
        float* pb2 = &Ws[bf][(bk + 8) * 136 + bc * 4];
        pb2[0] = to_tf32(rb1.x); pb2[1] = to_tf32(rb1.y); pb2[2] = to_tf32(rb1.z); pb2[3] = to_tf32(rb1.w);
    };
    lda(0); ldb(0); st(0); __syncthreads();
    for (int kc = 0; kc < NC; kc++) {
        int cur = kc & 1;
        if (kc + 1 < NC) { lda(kc + 1); ldb(kc + 1); }
#pragma unroll
        for (int kk = 0; kk < 2; kk++) {
            unsigned a[4];
            const int kb = kk * 8, rowb = wm * 16;
            a[0] = fau(As[cur][(rowb + gq) * 20 + kb + tq]);
            a[1] = fau(As[cur][(rowb + gq + 8) * 20 + kb + tq]);
            a[2] = fau(As[cur][(rowb + gq) * 20 + kb + tq + 4]);
            a[3] = fau(As[cur][(rowb + gq + 8) * 20 + kb + tq + 4]);
#pragma unroll
            for (int nf = 0; nf < 8; nf++) {
                const int nb = wn * 64 + nf * 8;
                unsigned bv[2] = { fau(Ws[cur][(kb + tq) * 136 + nb + gq]),
                                   fau(Ws[cur][(kb + tq + 4) * 136 + nb + gq]) };
                mma8(acc[nf], a, bv);
            }
        }
        if (kc + 1 < NC) st(cur ^ 1);
        __syncthreads();
    }
    const int row = r0 + wm * 16 + gq;
    if (EPI == 2) {
        float p0 = 0.f, p1 = 0.f;
#pragma unroll
        for (int nf = 0; nf < 8; nf++) {
            const int colb = n0 + wn * 64 + nf * 8 + 2 * tq;
            const float b0v = bias[colb], b1v = bias[colb + 1];
            float v0 = geluf(acc[nf][0] + b0v), v1 = geluf(acc[nf][1] + b1v);
            float v2 = geluf(acc[nf][2] + b0v), v3 = geluf(acc[nf][3] + b1v);
            p0 += v0 * g_Weh[colb] + v1 * g_Weh[colb + 1];
            p1 += v2 * g_Weh[colb] + v3 * g_Weh[colb + 1];
        }
        p0 += __shfl_xor_sync(0xffffffffu, p0, 1); p0 += __shfl_xor_sync(0xffffffffu, p0, 2);
        p1 += __shfl_xor_sync(0xffffffffu, p1, 1); p1 += __shfl_xor_sync(0xffffffffu, p1, 2);
        if (tq == 0) { atomicAdd(Y + row, p0); atomicAdd(Y + row + 8, p1); }
    } else {
#pragma unroll
        for (int nf = 0; nf < 8; nf++) {
            const int colb = n0 + wn * 64 + nf * 8 + 2 * tq;
            const float b0v = bias[colb], b1v = bias[colb + 1];
            float v0 = acc[nf][0] + b0v, v1 = acc[nf][1] + b1v;
            float v2 = acc[nf][2] + b0v, v3 = acc[nf][3] + b1v;
            if (EPI == 1) { v0 = splus(v0); v1 = splus(v1); v2 = splus(v2); v3 = splus(v3); }
            *(float2*)(C + (size_t)row * N + colb) = make_float2(v0, v1);
            *(float2*)(C + (size_t)(row + 8) * N + colb) = make_float2(v2, v3);
        }
    }
}

// ---------------- reparam sample ----------------
__global__ __launch_bounds__(256) void k_z(const float* __restrict__ out, const float* __restrict__ eps)
{
    int i = blockIdx.x * 256 + threadIdx.x;   // < 16777216
    int b = i >> 16, rem = i & 65535;
    int t = rem >> 7, l = rem & 127;
    size_t qi = ((size_t)b * TAc + t) * 128 + l;
    g_z[i] = out[OFF_QM + qi] + out[OFF_QS + qi] * eps[i];
}

// ---------------- host ----------------
extern "C" void kernel_launch(void* const* d_in, const int* in_sizes, int n_in,
                              void* d_out, int out_size)
{
    const float* ph   = (const float*)d_in[0];
    const float* pa   = (const float*)d_in[1];
    const float* eps  = (const float*)d_in[2];
    const float* We   = (const float*)d_in[3];
    const float* be   = (const float*)d_in[4];
    const float* Wihf = (const float*)d_in[5];
    const float* Whhf = (const float*)d_in[6];
    const float* bihf = (const float*)d_in[7];
    const float* bhhf = (const float*)d_in[8];
    const float* Wihb = (const float*)d_in[9];
    const float* Whhb = (const float*)d_in[10];
    const float* bihb = (const float*)d_in[11];
    const float* bhhb = (const float*)d_in[12];
    const float* Wqm  = (const float*)d_in[13];
    const float* bqm  = (const float*)d_in[14];
    const float* Wqs  = (const float*)d_in[15];
    const float* bqs  = (const float*)d_in[16];
    const float* Wihg = (const float*)d_in[17];
    const float* Whhg = (const float*)d_in[18];
    const float* bihg = (const float*)d_in[19];
    const float* bhhg = (const float*)d_in[20];
    const float* Wpm  = (const float*)d_in[21];
    const float* bpm  = (const float*)d_in[22];
    const float* Wps  = (const float*)d_in[23];
    const float* bps  = (const float*)d_in[24];
    const float* We1  = (const float*)d_in[25];
    const float* be1  = (const float*)d_in[26];
    const float* We2  = (const float*)d_in[27];
    const float* be2  = (const float*)d_in[28];
    const float* Whead= (const float*)d_in[29];
    const float* bhead= (const float*)d_in[30];
    float* out = (float*)d_out;

    float *xgf, *xgb, *xgg, *hbi, *zb, *Wf, *Wb, *Wg, *bf, *bb, *bg;
    cudaGetSymbolAddress((void**)&xgf, g_xgf);
    cudaGetSymbolAddress((void**)&xgb, g_xgb);
    cudaGetSymbolAddress((void**)&xgg, g_xgg);
    cudaGetSymbolAddress((void**)&hbi, g_hbi);
    cudaGetSymbolAddress((void**)&zb,  g_z);
    cudaGetSymbolAddress((void**)&Wf,  g_Wf);
    cudaGetSymbolAddress((void**)&Wb,  g_Wb);
    cudaGetSymbolAddress((void**)&Wg,  g_Wg);
    cudaGetSymbolAddress((void**)&bf,  g_bf);
    cudaGetSymbolAddress((void**)&bb,  g_bb);
    cudaGetSymbolAddress((void**)&bg,  g_bg);

    k_fuse<<<256, 256>>>(We, be, Wihf, bihf, Wihb, bihb, Wihg, bihg, We2, be2, Whead, bhead);
    k_init<<<512, 256>>>(out);

    // input gates (fused embedding), K=16
    k_xg<<<147456, 256>>>(pa, Wf, bf, xgf, BB * TAc, 1024);
    k_xg<<<147456, 256>>>(pa, Wb, bb, xgb, BB * TAc, 1024);
    k_xg<<<196608, 256>>>(ph, Wg, bg, xgg, BB * THc, 1536);

    // recurrences (576 steps; LSTM fwd/bwd + GRU fused per launch; 128 active CTAs)
    for (int s = 0; s < 576; s++)
        k_step<<<dim3(8, 8, 3), 256>>>(s, Whhf, bhhf, Whhb, bhhb, Whhg, bhhg, out);

    // heads
    k_gemm<0, 0><<<dim3(2304, 1), 256>>>(hbi, nullptr, Wqm, bqm, out + OFF_QM, nullptr, BB * TAc, 128, 512);
    k_gemm<1, 0><<<dim3(2304, 1), 256>>>(hbi, nullptr, Wqs, bqs, out + OFF_QS, nullptr, BB * TAc, 128, 512);
    k_gemm<0, 0><<<dim3(2048, 1), 256>>>(out + OFF_HS, nullptr, Wpm, bpm, out + OFF_PM, nullptr, BB * THc, 128, 512);
    k_gemm<1, 0><<<dim3(2048, 1), 256>>>(out + OFF_HS, nullptr, Wps, bps, out + OFF_PS, nullptr, BB * THc, 128, 512);

    // reparam + emission (gelu GEMM fused with folded head dot)
    k_z<<<65536, 256>>>(out, eps);
    k_gemm<2, 1><<<dim3(2048, 4), 256>>>(out + OFF_HS, zb, We1, be1, nullptr, out, BB * THc, 512, 640);
}

// round 13
// speedup vs baseline: 1.5098x; 1.3776x over previous
#include <cuda_runtime.h>
#include <math.h>
#include <stdint.h>

#define DI __device__ __forceinline__

#define BB 256
#define THc 512
#define TAc 576

// output section offsets (floats): y, prior_m, prior_s, qm_all, qs_all, h_seq
#define OFF_PM ((size_t)131072)
#define OFF_PS ((size_t)16908288)
#define OFF_QM ((size_t)33685504)
#define OFF_QS ((size_t)52559872)
#define OFF_HS ((size_t)71434240)

// ---------------- scratch ----------------
__device__ float g_xgf[(size_t)BB * TAc * 1024];
__device__ float g_xgb[(size_t)BB * TAc * 1024];
__device__ float g_xgg[(size_t)BB * THc * 1536];
__device__ float g_hbi[(size_t)BB * TAc * 512];
__device__ float g_z[(size_t)BB * THc * 128];
__device__ float g_hst[2][2][65536];   // [dir][parity][b*256+h]
__device__ float g_hg[2][131072];      // [parity][b*512+h]
__device__ float g_cst[2 * 65536];
__device__ float g_Wf[16 * 1024], g_Wb[16 * 1024], g_Wg[16 * 1536];
__device__ float g_bf[1024], g_bb[1024], g_bg[1536];
__device__ float g_Weh[512];
__device__ float g_yb[1];
__device__ unsigned g_bar[3];
__device__ unsigned g_gen[3];

// ---------------- helpers ----------------
DI float to_tf32(float x) { unsigned u; asm("cvt.rna.tf32.f32 %0, %1;" : "=r"(u) : "f"(x)); return __uint_as_float(u); }
DI unsigned fau(float x) { return __float_as_uint(x); }
DI void mma8(float* c, const unsigned* a, const unsigned* b) {
    asm volatile("mma.sync.aligned.m16n8k8.row.col.f32.tf32.tf32.f32 "
                 "{%0,%1,%2,%3},{%4,%5,%6,%7},{%8,%9},{%0,%1,%2,%3};\n"
                 : "+f"(c[0]), "+f"(c[1]), "+f"(c[2]), "+f"(c[3])
                 : "r"(a[0]), "r"(a[1]), "r"(a[2]), "r"(a[3]), "r"(b[0]), "r"(b[1]));
}
DI float sigf(float x) { return 1.f / (1.f + expf(-x)); }
DI float splus(float x) { return (x > 20.f ? x : log1pf(expf(x))) + 1e-5f; }
DI float geluf(float x) { return 0.5f * x * (1.f + erff(x * 0.70710678f)); }

// per-chain grid barrier (sense via generation counter). All CTAs co-resident.
DI void chain_bar(int c, unsigned n) {
    __syncthreads();
    if (threadIdx.x == 0) {
        __threadfence();
        unsigned gen = *((volatile unsigned*)&g_gen[c]);
        if (atomicAdd(&g_bar[c], 1u) == n - 1u) {
            *((volatile unsigned*)&g_bar[c]) = 0u;
            __threadfence();
            atomicAdd(&g_gen[c], 1u);
        } else {
            while (*((volatile unsigned*)&g_gen[c]) == gen) __nanosleep(64);
        }
        __threadfence();
    }
    __syncthreads();
}

// ---------------- weight folding ----------------
__global__ __launch_bounds__(256) void k_fuse(
    const float* We, const float* be,
    const float* Wihf, const float* bihf, const float* Wihb, const float* bihb,
    const float* Wihg, const float* bihg,
    const float* We2, const float* be2, const float* Whead, const float* bhead)
{
    int o = blockIdx.x * 256 + threadIdx.x;
    if (o < 16384) { int p = o >> 10, n = o & 1023; float a = 0.f;
        for (int d = 0; d < 512; d++) a += We[p * 512 + d] * Wihf[d * 1024 + n];
        g_Wf[o] = a; return; }
    o -= 16384;
    if (o < 16384) { int p = o >> 10, n = o & 1023; float a = 0.f;
        for (int d = 0; d < 512; d++) a += We[p * 512 + d] * Wihb[d * 1024 + n];
        g_Wb[o] = a; return; }
    o -= 16384;
    if (o < 24576) { int p = o / 1536, n = o - p * 1536; float a = 0.f;
        for (int d = 0; d < 512; d++) a += We[p * 512 + d] * Wihg[d * 1536 + n];
        g_Wg[o] = a; return; }
    o -= 24576;
    if (o < 1024) { float a = bihf[o];
        for (int d = 0; d < 512; d++) a += be[d] * Wihf[d * 1024 + o];
        g_bf[o] = a; return; }
    o -= 1024;
    if (o < 1024) { float a = bihb[o];
        for (int d = 0; d < 512; d++) a += be[d] * Wihb[d * 1024 + o];
        g_bb[o] = a; return; }
    o -= 1024;
    if (o < 1536) { float a = bihg[o];
        for (int d = 0; d < 512; d++) a += be[d] * Wihg[d * 1536 + o];
        g_bg[o] = a; return; }
    o -= 1536;
    if (o < 512) { float a = 0.f;
        for (int j = 0; j < 512; j++) a += We2[o * 512 + j] * Whead[j];
        g_Weh[o] = a; return; }
    o -= 512;
    if (o == 0) { float a = bhead[0];
        for (int j = 0; j < 512; j++) a += be2[j] * Whead[j];
        g_yb[0] = a; }
}

__global__ __launch_bounds__(256) void k_init(float* Y)
{
    int i = blockIdx.x * 256 + threadIdx.x;
    if (i < 131072) {
        Y[i] = g_yb[0];
        g_cst[i] = 0.f;
        g_hg[0][i] = 0.f;
        if (i < 65536) { g_hst[0][0][i] = 0.f; g_hst[1][0][i] = 0.f; }
        if (i < 3) { g_bar[i] = 0u; g_gen[i] = 0u; }
    }
}

// ---------------- input-gate GEMM, K=16, 8 rows per CTA (A staged in smem) ----------------
__global__ __launch_bounds__(256) void k_xg(
    const float* __restrict__ A, const float* __restrict__ W,
    const float* __restrict__ bias, float* __restrict__ C, int N)
{
    __shared__ float as[8][16];
    int r0 = blockIdx.x * 8;
    int tid = threadIdx.x;
    if (tid < 128) {
        int rr = tid >> 4, pp = tid & 15;
        as[rr][pp] = A[(size_t)(r0 + rr) * 16 + pp];
    }
    __syncthreads();
    int nq = N >> 2;
    for (int c = tid; c < nq; c += 256) {
        float4 b = *(const float4*)(bias + c * 4);
        float4 acc[8];
#pragma unroll
        for (int rr = 0; rr < 8; rr++) acc[rr] = b;
#pragma unroll
        for (int p = 0; p < 16; p++) {
            float4 w = *(const float4*)(W + (size_t)p * N + c * 4);
#pragma unroll
            for (int rr = 0; rr < 8; rr++) {
                float a = as[rr][p];
                acc[rr].x += a * w.x; acc[rr].y += a * w.y; acc[rr].z += a * w.z; acc[rr].w += a * w.w;
            }
        }
#pragma unroll
        for (int rr = 0; rr < 8; rr++)
            *(float4*)(C + (size_t)(r0 + rr) * N + c * 4) = acc[rr];
    }
}

// ---------------- recurrence GEMM core (32-row tiles, double-buffered) ----------------
template <int NG>
DI void rec_gemm(float (&acc)[2][NG][4], float (*As)[32][20], float (*Bs)[16][264],
                 const float* hst, const float* W, int ldw, int K, int gstride,
                 int b0, int colbase, int tid, int wm, int wn, int gq, int tq)
{
    float2 va; float4 vb[NG];
    int r = tid >> 3, q = (tid & 7) * 2;
    int r2 = tid >> 4, qq = tid & 15;
    auto ld = [&](int kc) {
        va = *(const float2*)(hst + (size_t)(b0 + r) * K + kc * 16 + q);
#pragma unroll
        for (int qi = 0; qi < NG; qi++) {
            int c4 = qq + qi * 16; int g = c4 >> 4; int jj = (c4 & 15) * 4;
            vb[qi] = *(const float4*)(W + (size_t)(kc * 16 + r2) * ldw + g * gstride + colbase + jj);
        }
    };
    auto st = [&](int bf) {
        As[bf][r][q] = to_tf32(va.x); As[bf][r][q + 1] = to_tf32(va.y);
#pragma unroll
        for (int qi = 0; qi < NG; qi++) {
            int c4 = qq + qi * 16; float* p = &Bs[bf][r2][c4 * 4];
            p[0] = to_tf32(vb[qi].x); p[1] = to_tf32(vb[qi].y); p[2] = to_tf32(vb[qi].z); p[3] = to_tf32(vb[qi].w);
        }
    };
    ld(0); st(0); __syncthreads();
    int NC = K >> 4;
    for (int kc = 0; kc < NC; kc++) {
        int cur = kc & 1;
        if (kc + 1 < NC) ld(kc + 1);
#pragma unroll
        for (int kk = 0; kk < 2; kk++) {
            int kb = kk * 8; unsigned a[4];
            int rb = wm * 16;
            a[0] = fau(As[cur][rb + gq][kb + tq]);     a[1] = fau(As[cur][rb + gq + 8][kb + tq]);
            a[2] = fau(As[cur][rb + gq][kb + tq + 4]); a[3] = fau(As[cur][rb + gq + 8][kb + tq + 4]);
#pragma unroll
            for (int g = 0; g < NG; g++)
#pragma unroll
            for (int nn = 0; nn < 2; nn++) {
                int pc = g * 64 + wn * 16 + nn * 8 + gq;
                unsigned bv[2] = { fau(Bs[cur][kb + tq][pc]), fau(Bs[cur][kb + tq + 4][pc]) };
                mma8(acc[nn][g], a, bv);
            }
        }
        if (kc + 1 < NC) st(cur ^ 1);
        __syncthreads();
    }
}

// ---------------- persistent recurrence: 3 chains, grid barriers ----------------
__global__ __launch_bounds__(256) void k_rec(
    const float* __restrict__ Whf, const float* __restrict__ bhf,
    const float* __restrict__ Whb, const float* __restrict__ bhb,
    const float* __restrict__ Whg, const float* __restrict__ bhg,
    float* __restrict__ out)
{
    __shared__ float As[2][32][20];
    __shared__ float Bs[2][16][264];
    int bid = blockIdx.x;
    int tid = threadIdx.x, wid = tid >> 5, lane = tid & 31, gq = lane >> 2, tq = lane & 3;
    int wm = wid >> 2, wn = wid & 3;
    if (bid < 64) {
        // LSTM chains: z=0 fwd (CTAs 0..31), z=1 bwd (32..63); 8 bx x 4 by
        int z = bid >> 5;
        int l = bid & 31;
        int b0 = (l & 7) * 32, colbase = (l >> 3) * 64;
        const float* Whh = z ? Whb : Whf;
        const float* bhh = z ? bhb : bhf;
        float* cst = g_cst + z * 65536;
        const float* xg = z ? g_xgb : g_xgf;
        for (int s = 0; s < 576; s++) {
            int t = z ? 575 - s : s;
            int pr = s & 1, pw = pr ^ 1;
            const float* hrd = g_hst[z][pr];
            float* hwr = g_hst[z][pw];
            float acc[2][4][4];
#pragma unroll
            for (int nn = 0; nn < 2; nn++)
                for (int g = 0; g < 4; g++) for (int j = 0; j < 4; j++) acc[nn][g][j] = 0.f;
            rec_gemm<4>(acc, As, Bs, hrd, Whh, 1024, 256, 256, b0, colbase, tid, wm, wn, gq, tq);
#pragma unroll
            for (int nn = 0; nn < 2; nn++)
#pragma unroll
            for (int half = 0; half < 2; half++) {
                int ci = half * 2;
                int r = b0 + wm * 16 + gq + half * 8;
                int hcol = colbase + wn * 16 + nn * 8 + 2 * tq;
                size_t xb = ((size_t)r * TAc + t) * 1024;
                float gv[4][2];
#pragma unroll
                for (int g = 0; g < 4; g++) {
                    int c = g * 256 + hcol;
                    gv[g][0] = acc[nn][g][ci]     + xg[xb + c]     + bhh[c];
                    gv[g][1] = acc[nn][g][ci + 1] + xg[xb + c + 1] + bhh[c + 1];
                }
                size_t si = (size_t)r * 256 + hcol;
                size_t oi = ((size_t)r * TAc + t) * 512 + z * 256 + hcol;
#pragma unroll
                for (int j = 0; j < 2; j++) {
                    float cn = sigf(gv[1][j]) * cst[si + j] + sigf(gv[0][j]) * tanhf(gv[2][j]);
                    float hv = sigf(gv[3][j]) * tanhf(cn);
                    cst[si + j] = cn; hwr[si + j] = hv;
                    g_hbi[oi + j] = hv;
                }
            }
            chain_bar(z, 32);
        }
    } else {
        // GRU chain: CTAs 64..127; 8 bx x 8 by
        int l = bid - 64;
        int b0 = (l & 7) * 32, colbase = (l >> 3) * 64;
        const float* xg = g_xgg;
        for (int s = 0; s < 512; s++) {
            int pr = s & 1, pw = pr ^ 1;
            const float* ghr = g_hg[pr];
            float* ghw = g_hg[pw];
            float acc[2][3][4];
#pragma unroll
            for (int nn = 0; nn < 2; nn++)
                for (int g = 0; g < 3; g++) for (int j = 0; j < 4; j++) acc[nn][g][j] = 0.f;
            rec_gemm<3>(acc, As, Bs, ghr, Whg, 1536, 512, 512, b0, colbase, tid, wm, wn, gq, tq);
#pragma unroll
            for (int nn = 0; nn < 2; nn++)
#pragma unroll
            for (int half = 0; half < 2; half++) {
                int ci = half * 2;
                int r = b0 + wm * 16 + gq + half * 8;
                int hcol = colbase + wn * 16 + nn * 8 + 2 * tq;
                size_t xb = ((size_t)r * THc + s) * 1536;
                size_t si = (size_t)r * 512 + hcol;
                size_t oi = OFF_HS + ((size_t)r * THc + s) * 512 + hcol;
#pragma unroll
                for (int j = 0; j < 2; j++) {
                    float hr = acc[nn][0][ci + j] + bhg[hcol + j];
                    float hz = acc[nn][1][ci + j] + bhg[512 + hcol + j];
                    float hn = acc[nn][2][ci + j] + bhg[1024 + hcol + j];
                    float rv = sigf(xg[xb + hcol + j] + hr);
                    float zv = sigf(xg[xb + 512 + hcol + j] + hz);
                    float nv = tanhf(xg[xb + 1024 + hcol + j] + rv * hn);
                    float hv = (1.f - zv) * nv + zv * ghr[si + j];
                    ghw[si + j] = hv;
                    out[oi + j] = hv;
                }
            }
            chain_bar(2, 64);
        }
    }
}

// ---------------- generic tf32 GEMM 64x128x16 tiles, double-buffered ----------------
template <int EPI, int CAT>
__global__ __launch_bounds__(256) void k_gemm(
    const float* __restrict__ A, const float* __restrict__ Az,
    const float* __restrict__ W, const float* __restrict__ bias,
    float* __restrict__ C, float* __restrict__ Y, int M, int N, int K)
{
    __shared__ float As[2][64 * 20];
    __shared__ float Ws[2][16 * 136];
    const int tid = threadIdx.x, wid = tid >> 5, lane = tid & 31;
    const int gq = lane >> 2, tq = lane & 3;
    const int wm = wid >> 1, wn = wid & 1;
    const int r0 = blockIdx.x * 64, n0 = blockIdx.y * 128;
    const int ar = tid >> 2, aq = tid & 3;
    const int bk = tid >> 5, bc = tid & 31;
    const int ldA = CAT ? 512 : K;

    float acc[8][4];
#pragma unroll
    for (int i = 0; i < 8; i++) for (int q = 0; q < 4; q++) acc[i][q] = 0.f;

    float4 ra, rb0, rb1;
    const int NC = K >> 4;
    auto lda = [&](int kc) {
        int k = kc * 16 + aq * 4;
        const float* p = (CAT && k >= 512) ? (Az + (size_t)(r0 + ar) * 128 + (k - 512))
                                           : (A + (size_t)(r0 + ar) * ldA + k);
        ra = *(const float4*)p;
    };
    auto ldb = [&](int kc) {
        rb0 = *(const float4*)(W + (size_t)(kc * 16 + bk) * N + n0 + bc * 4);
        rb1 = *(const float4*)(W + (size_t)(kc * 16 + bk + 8) * N + n0 + bc * 4);
    };
    auto st = [&](int bf) {
        float* pa = &As[bf][ar * 20 + aq * 4];
        pa[0] = to_tf32(ra.x); pa[1] = to_tf32(ra.y); pa[2] = to_tf32(ra.z); pa[3] = to_tf32(ra.w);
        float* pb = &Ws[bf][bk * 136 + bc * 4];
        pb[0] = to_tf32(rb0.x); pb[1] = to_tf32(rb0.y); pb[2] = to_tf32(rb0.z); pb[3] = to_tf32(rb0.w);
        float* pb2 = &Ws[bf][(bk + 8) * 136 + bc * 4];
        pb2[0] = to_tf32(rb1.x); pb2[1] = to_tf32(rb1.y); pb2[2] = to_tf32(rb1.z); pb2[3] = to_tf32(rb1.w);
    };
    lda(0); ldb(0); st(0); __syncthreads();
    for (int kc = 0; kc < NC; kc++) {
        int cur = kc & 1;
        if (kc + 1 < NC) { lda(kc + 1); ldb(kc + 1); }
#pragma unroll
        for (int kk = 0; kk < 2; kk++) {
            unsigned a[4];
            const int kb = kk * 8, rowb = wm * 16;
            a[0] = fau(As[cur][(rowb + gq) * 20 + kb + tq]);
            a[1] = fau(As[cur][(rowb + gq + 8) * 20 + kb + tq]);
            a[2] = fau(As[cur][(rowb + gq) * 20 + kb + tq + 4]);
            a[3] = fau(As[cur][(rowb + gq + 8) * 20 + kb + tq + 4]);
#pragma unroll
            for (int nf = 0; nf < 8; nf++) {
                const int nb = wn * 64 + nf * 8;
                unsigned bv[2] = { fau(Ws[cur][(kb + tq) * 136 + nb + gq]),
                                   fau(Ws[cur][(kb + tq + 4) * 136 + nb + gq]) };
                mma8(acc[nf], a, bv);
            }
        }
        if (kc + 1 < NC) st(cur ^ 1);
        __syncthreads();
    }
    const int row = r0 + wm * 16 + gq;
    if (EPI == 2) {
        float p0 = 0.f, p1 = 0.f;
#pragma unroll
        for (int nf = 0; nf < 8; nf++) {
            const int colb = n0 + wn * 64 + nf * 8 + 2 * tq;
            const float b0v = bias[colb], b1v = bias[colb + 1];
            float v0 = geluf(acc[nf][0] + b0v), v1 = geluf(acc[nf][1] + b1v);
            float v2 = geluf(acc[nf][2] + b0v), v3 = geluf(acc[nf][3] + b1v);
            p0 += v0 * g_Weh[colb] + v1 * g_Weh[colb + 1];
            p1 += v2 * g_Weh[colb] + v3 * g_Weh[colb + 1];
        }
        p0 += __shfl_xor_sync(0xffffffffu, p0, 1); p0 += __shfl_xor_sync(0xffffffffu, p0, 2);
        p1 += __shfl_xor_sync(0xffffffffu, p1, 1); p1 += __shfl_xor_sync(0xffffffffu, p1, 2);
        if (tq == 0) { atomicAdd(Y + row, p0); atomicAdd(Y + row + 8, p1); }
    } else {
#pragma unroll
        for (int nf = 0; nf < 8; nf++) {
            const int colb = n0 + wn * 64 + nf * 8 + 2 * tq;
            const float b0v = bias[colb], b1v = bias[colb + 1];
            float v0 = acc[nf][0] + b0v, v1 = acc[nf][1] + b1v;
            float v2 = acc[nf][2] + b0v, v3 = acc[nf][3] + b1v;
            if (EPI == 1) { v0 = splus(v0); v1 = splus(v1); v2 = splus(v2); v3 = splus(v3); }
            *(float2*)(C + (size_t)row * N + colb) = make_float2(v0, v1);
            *(float2*)(C + (size_t)(row + 8) * N + colb) = make_float2(v2, v3);
        }
    }
}

// ---------------- reparam sample ----------------
__global__ __launch_bounds__(256) void k_z(const float* __restrict__ out, const float* __restrict__ eps)
{
    int i = blockIdx.x * 256 + threadIdx.x;
    int b = i >> 16, rem = i & 65535;
    int t = rem >> 7, l = rem & 127;
    size_t qi = ((size_t)b * TAc + t) * 128 + l;
    g_z[i] = out[OFF_QM + qi] + out[OFF_QS + qi] * eps[i];
}

// ---------------- host ----------------
extern "C" void kernel_launch(void* const* d_in, const int* in_sizes, int n_in,
                              void* d_out, int out_size)
{
    const float* ph   = (const float*)d_in[0];
    const float* pa   = (const float*)d_in[1];
    const float* eps  = (const float*)d_in[2];
    const float* We   = (const float*)d_in[3];
    const float* be   = (const float*)d_in[4];
    const float* Wihf = (const float*)d_in[5];
    const float* Whhf = (const float*)d_in[6];
    const float* bihf = (const float*)d_in[7];
    const float* bhhf = (const float*)d_in[8];
    const float* Wihb = (const float*)d_in[9];
    const float* Whhb = (const float*)d_in[10];
    const float* bihb = (const float*)d_in[11];
    const float* bhhb = (const float*)d_in[12];
    const float* Wqm  = (const float*)d_in[13];
    const float* bqm  = (const float*)d_in[14];
    const float* Wqs  = (const float*)d_in[15];
    const float* bqs  = (const float*)d_in[16];
    const float* Wihg = (const float*)d_in[17];
    const float* Whhg = (const float*)d_in[18];
    const float* bihg = (const float*)d_in[19];
    const float* bhhg = (const float*)d_in[20];
    const float* Wpm  = (const float*)d_in[21];
    const float* bpm  = (const float*)d_in[22];
    const float* Wps  = (const float*)d_in[23];
    const float* bps  = (const float*)d_in[24];
    const float* We1  = (const float*)d_in[25];
    const float* be1  = (const float*)d_in[26];
    const float* We2  = (const float*)d_in[27];
    const float* be2  = (const float*)d_in[28];
    const float* Whead= (const float*)d_in[29];
    const float* bhead= (const float*)d_in[30];
    float* out = (float*)d_out;

    float *xgf, *xgb, *xgg, *hbi, *zb, *Wf, *Wb, *Wg, *bf, *bb, *bg;
    cudaGetSymbolAddress((void**)&xgf, g_xgf);
    cudaGetSymbolAddress((void**)&xgb, g_xgb);
    cudaGetSymbolAddress((void**)&xgg, g_xgg);
    cudaGetSymbolAddress((void**)&hbi, g_hbi);
    cudaGetSymbolAddress((void**)&zb,  g_z);
    cudaGetSymbolAddress((void**)&Wf,  g_Wf);
    cudaGetSymbolAddress((void**)&Wb,  g_Wb);
    cudaGetSymbolAddress((void**)&Wg,  g_Wg);
    cudaGetSymbolAddress((void**)&bf,  g_bf);
    cudaGetSymbolAddress((void**)&bb,  g_bb);
    cudaGetSymbolAddress((void**)&bg,  g_bg);

    k_fuse<<<256, 256>>>(We, be, Wihf, bihf, Wihb, bihb, Wihg, bihg, We2, be2, Whead, bhead);
    k_init<<<512, 256>>>(out);

    // input gates (fused embedding), K=16, 8 rows/CTA
    k_xg<<<18432, 256>>>(pa, Wf, bf, xgf, 1024);
    k_xg<<<18432, 256>>>(pa, Wb, bb, xgb, 1024);
    k_xg<<<16384, 256>>>(ph, Wg, bg, xgg, 1536);

    // persistent recurrence: 3 independent chains, per-chain grid barriers
    k_rec<<<128, 256>>>(Whhf, bhhf, Whhb, bhhb, Whhg, bhhg, out);

    // heads
    k_gemm<0, 0><<<dim3(2304, 1), 256>>>(hbi, nullptr, Wqm, bqm, out + OFF_QM, nullptr, BB * TAc, 128, 512);
    k_gemm<1, 0><<<dim3(2304, 1), 256>>>(hbi, nullptr, Wqs, bqs, out + OFF_QS, nullptr, BB * TAc, 128, 512);
    k_gemm<0, 0><<<dim3(2048, 1), 256>>>(out + OFF_HS, nullptr, Wpm, bpm, out + OFF_PM, nullptr, BB * THc, 128, 512);
    k_gemm<1, 0><<<dim3(2048, 1), 256>>>(out + OFF_HS, nullptr, Wps, bps, out + OFF_PS, nullptr, BB * THc, 128, 512);

    // reparam + emission (gelu GEMM fused with folded head dot)
    k_z<<<65536, 256>>>(out, eps);
    k_gemm<2, 1><<<dim3(2048, 4), 256>>>(out + OFF_HS, zb, We1, be1, nullptr, out, BB * THc, 512, 640);
}

// round 16
// speedup vs baseline: 2.2443x; 1.4865x over previous
#include <cuda_runtime.h>
#include <math.h>
#include <stdint.h>

#define DI __device__ __forceinline__

#define BB 256
#define THc 512
#define TAc 576

// output section offsets (floats): y, prior_m, prior_s, qm_all, qs_all, h_seq
#define OFF_PM ((size_t)131072)
#define OFF_PS ((size_t)16908288)
#define OFF_QM ((size_t)33685504)
#define OFF_QS ((size_t)52559872)
#define OFF_HS ((size_t)71434240)

// ---------------- scratch ----------------
__device__ float g_xgf[(size_t)BB * TAc * 1024];
__device__ float g_xgb[(size_t)BB * TAc * 1024];
__device__ float g_xgg[(size_t)BB * THc * 1536];
__device__ float g_hbi[(size_t)BB * TAc * 512];
__device__ float g_z[(size_t)BB * THc * 128];
__device__ float g_hst[2][2][65536];   // [dir][parity] rounded h (GEMM input)
__device__ float g_hg[2][131072];      // [parity] exact GRU h (update input)
__device__ float g_hgr[2][131072];     // [parity] rounded GRU h (GEMM input)
__device__ float g_cst[2 * 65536];
__device__ float g_Wf[16 * 1024], g_Wb[16 * 1024], g_Wg[16 * 1536];
__device__ float g_bf[1024], g_bb[1024], g_bg[1536];
__device__ float g_Wfr[256 * 1024], g_Wbr[256 * 1024], g_Wgr[512 * 1536]; // tf32-rounded Whh
__device__ float g_Weh[512];
__device__ float g_yb[1];
__device__ unsigned g_bar[3];
__device__ unsigned g_gen[3];

// ---------------- helpers ----------------
DI float to_tf32(float x) { unsigned u; asm("cvt.rna.tf32.f32 %0, %1;" : "=r"(u) : "f"(x)); return __uint_as_float(u); }
DI unsigned fau(float x) { return __float_as_uint(x); }
DI void mma8(float* c, const unsigned* a, const unsigned* b) {
    asm volatile("mma.sync.aligned.m16n8k8.row.col.f32.tf32.tf32.f32 "
                 "{%0,%1,%2,%3},{%4,%5,%6,%7},{%8,%9},{%0,%1,%2,%3};\n"
                 : "+f"(c[0]), "+f"(c[1]), "+f"(c[2]), "+f"(c[3])
                 : "r"(a[0]), "r"(a[1]), "r"(a[2]), "r"(a[3]), "r"(b[0]), "r"(b[1]));
}
DI void cp16(void* dst, const void* src) {
    unsigned d = (unsigned)__cvta_generic_to_shared(dst);
    asm volatile("cp.async.cg.shared.global [%0], [%1], 16;\n" :: "r"(d), "l"(src));
}
DI void cp_commit() { asm volatile("cp.async.commit_group;\n"); }
DI void cp_wait1() { asm volatile("cp.async.wait_group 1;\n"); }
DI float sigf(float x) { return 1.f / (1.f + expf(-x)); }
DI float splus(float x) { return (x > 20.f ? x : log1pf(expf(x))) + 1e-5f; }
DI float geluf(float x) { return 0.5f * x * (1.f + erff(x * 0.70710678f)); }

// per-chain grid barrier
DI void chain_bar(int c, unsigned n) {
    __syncthreads();
    if (threadIdx.x == 0) {
        __threadfence();
        unsigned gen = *((volatile unsigned*)&g_gen[c]);
        if (atomicAdd(&g_bar[c], 1u) == n - 1u) {
            *((volatile unsigned*)&g_bar[c]) = 0u;
            __threadfence();
            atomicAdd(&g_gen[c], 1u);
        } else {
            while (*((volatile unsigned*)&g_gen[c]) == gen) __nanosleep(64);
        }
        __threadfence();
    }
    __syncthreads();
}

// ---------------- weight folding ----------------
__global__ __launch_bounds__(256) void k_fuse(
    const float* We, const float* be,
    const float* Wihf, const float* bihf, const float* Wihb, const float* bihb,
    const float* Wihg, const float* bihg,
    const float* We2, const float* be2, const float* Whead, const float* bhead)
{
    int o = blockIdx.x * 256 + threadIdx.x;
    if (o < 16384) { int p = o >> 10, n = o & 1023; float a = 0.f;
        for (int d = 0; d < 512; d++) a += We[p * 512 + d] * Wihf[d * 1024 + n];
        g_Wf[o] = a; return; }
    o -= 16384;
    if (o < 16384) { int p = o >> 10, n = o & 1023; float a = 0.f;
        for (int d = 0; d < 512; d++) a += We[p * 512 + d] * Wihb[d * 1024 + n];
        g_Wb[o] = a; return; }
    o -= 16384;
    if (o < 24576) { int p = o / 1536, n = o - p * 1536; float a = 0.f;
        for (int d = 0; d < 512; d++) a += We[p * 512 + d] * Wihg[d * 1536 + n];
        g_Wg[o] = a; return; }
    o -= 24576;
    if (o < 1024) { float a = bihf[o];
        for (int d = 0; d < 512; d++) a += be[d] * Wihf[d * 1024 + o];
        g_bf[o] = a; return; }
    o -= 1024;
    if (o < 1024) { float a = bihb[o];
        for (int d = 0; d < 512; d++) a += be[d] * Wihb[d * 1024 + o];
        g_bb[o] = a; return; }
    o -= 1024;
    if (o < 1536) { float a = bihg[o];
        for (int d = 0; d < 512; d++) a += be[d] * Wihg[d * 1536 + o];
        g_bg[o] = a; return; }
    o -= 1536;
    if (o < 512) { float a = 0.f;
        for (int j = 0; j < 512; j++) a += We2[o * 512 + j] * Whead[j];
        g_Weh[o] = a; return; }
    o -= 512;
    if (o == 0) { float a = bhead[0];
        for (int j = 0; j < 512; j++) a += be2[j] * Whead[j];
        g_yb[0] = a; }
}

// pre-round recurrent weights to tf32 (so cp.async copies raw bytes)
__global__ __launch_bounds__(256) void k_round(
    const float* Whf, const float* Whb, const float* Whg)
{
    int i = blockIdx.x * 256 + threadIdx.x;
    if (i < 262144) { g_Wfr[i] = to_tf32(Whf[i]); g_Wbr[i] = to_tf32(Whb[i]); }
    if (i < 786432) g_Wgr[i] = to_tf32(Whg[i]);
}

__global__ __launch_bounds__(256) void k_init(float* Y)
{
    int i = blockIdx.x * 256 + threadIdx.x;
    if (i < 131072) {
        Y[i] = g_yb[0];
        g_cst[i] = 0.f;
        g_hg[0][i] = 0.f; g_hgr[0][i] = 0.f;
        if (i < 65536) { g_hst[0][0][i] = 0.f; g_hst[1][0][i] = 0.f; }
        if (i < 3) { g_bar[i] = 0u; g_gen[i] = 0u; }
    }
}

// ---------------- input-gate GEMM, K=16, 8 rows per CTA ----------------
__global__ __launch_bounds__(256) void k_xg(
    const float* __restrict__ A, const float* __restrict__ W,
    const float* __restrict__ bias, float* __restrict__ C, int N)
{
    __shared__ float as[8][16];
    int r0 = blockIdx.x * 8;
    int tid = threadIdx.x;
    if (tid < 128) {
        int rr = tid >> 4, pp = tid & 15;
        as[rr][pp] = A[(size_t)(r0 + rr) * 16 + pp];
    }
    __syncthreads();
    int nq = N >> 2;
    for (int c = tid; c < nq; c += 256) {
        float4 b = *(const float4*)(bias + c * 4);
        float4 acc[8];
#pragma unroll
        for (int rr = 0; rr < 8; rr++) acc[rr] = b;
#pragma unroll
        for (int p = 0; p < 16; p++) {
            float4 w = *(const float4*)(W + (size_t)p * N + c * 4);
#pragma unroll
            for (int rr = 0; rr < 8; rr++) {
                float a = as[rr][p];
                acc[rr].x += a * w.x; acc[rr].y += a * w.y; acc[rr].z += a * w.z; acc[rr].w += a * w.w;
            }
        }
#pragma unroll
        for (int rr = 0; rr < 8; rr++)
            *(float4*)(C + (size_t)(r0 + rr) * N + c * 4) = acc[rr];
    }
}

// ---------------- recurrence GEMM core: cp.async 3-stage pipeline ----------------
// A: 32xK rounded state; B: gate-aligned rounded W slice. One barrier per chunk.
template <int NG>
DI void rec_gemm(float (&acc)[2][NG][4], float (*As)[32][20], float (*Bs)[16][264],
                 const float* hst, const float* Wr, int ldw, int K, int gstride,
                 int b0, int colbase, int tid, int wm, int wn, int gq, int tq)
{
    const int NC = K >> 4;
    auto issue = [&](int kc) {
        int s = kc % 3;
        if (tid < 128) {
            int row = tid >> 2, q4 = tid & 3;
            cp16(&As[s][row][q4 * 4], hst + (size_t)(b0 + row) * K + kc * 16 + q4 * 4);
        }
        int row = tid >> 4, qq = tid & 15;
        const float* base = Wr + (size_t)(kc * 16 + row) * ldw + colbase + qq * 4;
#pragma unroll
        for (int qi = 0; qi < NG; qi++)
            cp16(&Bs[s][row][(qq + qi * 16) * 4], base + qi * gstride);
        cp_commit();
    };
    issue(0); issue(1);
    for (int kc = 0; kc < NC; kc++) {
        int cur = kc % 3;
        cp_wait1();
        __syncthreads();
#pragma unroll
        for (int kk = 0; kk < 2; kk++) {
            int kb = kk * 8; unsigned a[4];
            int rb = wm * 16;
            a[0] = fau(As[cur][rb + gq][kb + tq]);     a[1] = fau(As[cur][rb + gq + 8][kb + tq]);
            a[2] = fau(As[cur][rb + gq][kb + tq + 4]); a[3] = fau(As[cur][rb + gq + 8][kb + tq + 4]);
#pragma unroll
            for (int g = 0; g < NG; g++)
#pragma unroll
            for (int nn = 0; nn < 2; nn++) {
                int pc = g * 64 + wn * 16 + nn * 8 + gq;
                unsigned bv[2] = { fau(Bs[cur][kb + tq][pc]), fau(Bs[cur][kb + tq + 4][pc]) };
                mma8(acc[nn][g], a, bv);
            }
        }
        if (kc + 2 < NC) issue(kc + 2); else cp_commit();  // empty group keeps wait-count invariant
    }
}

// ---------------- persistent recurrence: 3 chains, grid barriers ----------------
__global__ __launch_bounds__(256) void k_rec(
    const float* __restrict__ bhf, const float* __restrict__ bhb,
    const float* __restrict__ bhg, float* __restrict__ out)
{
    extern __shared__ float dsm[];
    float (*As)[32][20] = (float(*)[32][20])dsm;
    float (*Bs)[16][264] = (float(*)[16][264])(dsm + 3 * 32 * 20);
    int bid = blockIdx.x;
    int tid = threadIdx.x, wid = tid >> 5, lane = tid & 31, gq = lane >> 2, tq = lane & 3;
    int wm = wid >> 2, wn = wid & 3;
    if (bid < 64) {
        int z = bid >> 5;
        int l = bid & 31;
        int b0 = (l & 7) * 32, colbase = (l >> 3) * 64;
        const float* Wr = z ? g_Wbr : g_Wfr;
        const float* bhh = z ? bhb : bhf;
        float* cst = g_cst + z * 65536;
        const float* xg = z ? g_xgb : g_xgf;
        for (int s = 0; s < 576; s++) {
            int t = z ? 575 - s : s;
            int pr = s & 1, pw = pr ^ 1;
            const float* hrd = g_hst[z][pr];
            float* hwr = g_hst[z][pw];
            // prefetch epilogue operands (hidden under GEMM)
            float xv[2][2][4][2]; float cv[2][2][2];
#pragma unroll
            for (int nn = 0; nn < 2; nn++)
#pragma unroll
            for (int half = 0; half < 2; half++) {
                int r = b0 + wm * 16 + gq + half * 8;
                int hcol = colbase + wn * 16 + nn * 8 + 2 * tq;
                size_t xb = ((size_t)r * TAc + t) * 1024;
#pragma unroll
                for (int g = 0; g < 4; g++) {
                    float2 v = *(const float2*)(xg + xb + g * 256 + hcol);
                    xv[nn][half][g][0] = v.x; xv[nn][half][g][1] = v.y;
                }
                float2 c = *(const float2*)(cst + (size_t)r * 256 + hcol);
                cv[nn][half][0] = c.x; cv[nn][half][1] = c.y;
            }
            float acc[2][4][4];
#pragma unroll
            for (int nn = 0; nn < 2; nn++)
                for (int g = 0; g < 4; g++) for (int j = 0; j < 4; j++) acc[nn][g][j] = 0.f;
            rec_gemm<4>(acc, As, Bs, hrd, Wr, 1024, 256, 256, b0, colbase, tid, wm, wn, gq, tq);
#pragma unroll
            for (int nn = 0; nn < 2; nn++)
#pragma unroll
            for (int half = 0; half < 2; half++) {
                int ci = half * 2;
                int r = b0 + wm * 16 + gq + half * 8;
                int hcol = colbase + wn * 16 + nn * 8 + 2 * tq;
                float gv[4][2];
#pragma unroll
                for (int g = 0; g < 4; g++) {
                    int c = g * 256 + hcol;
                    gv[g][0] = acc[nn][g][ci]     + xv[nn][half][g][0] + bhh[c];
                    gv[g][1] = acc[nn][g][ci + 1] + xv[nn][half][g][1] + bhh[c + 1];
                }
                size_t si = (size_t)r * 256 + hcol;
                size_t oi = ((size_t)r * TAc + t) * 512 + z * 256 + hcol;
                float hn2[2], cn2[2];
#pragma unroll
                for (int j = 0; j < 2; j++) {
                    float cn = sigf(gv[1][j]) * cv[nn][half][j] + sigf(gv[0][j]) * tanhf(gv[2][j]);
                    float hv = sigf(gv[3][j]) * tanhf(cn);
                    cn2[j] = cn; hn2[j] = hv;
                    hwr[si + j] = to_tf32(hv);
                }
                *(float2*)(cst + si) = make_float2(cn2[0], cn2[1]);
                *(float2*)(g_hbi + oi) = make_float2(hn2[0], hn2[1]);
            }
            chain_bar(z, 32);
        }
    } else {
        int l = bid - 64;
        int b0 = (l & 7) * 32, colbase = (l >> 3) * 64;
        const float* xg = g_xgg;
        for (int s = 0; s < 512; s++) {
            int pr = s & 1, pw = pr ^ 1;
            const float* ghr = g_hg[pr];
            float* ghw = g_hg[pw];
            float* ghwr = g_hgr[pw];
            float xv[2][2][3][2]; float hp[2][2][2];
#pragma unroll
            for (int nn = 0; nn < 2; nn++)
#pragma unroll
            for (int half = 0; half < 2; half++) {
                int r = b0 + wm * 16 + gq + half * 8;
                int hcol = colbase + wn * 16 + nn * 8 + 2 * tq;
                size_t xb = ((size_t)r * THc + s) * 1536;
#pragma unroll
                for (int g = 0; g < 3; g++) {
                    float2 v = *(const float2*)(xg + xb + g * 512 + hcol);
                    xv[nn][half][g][0] = v.x; xv[nn][half][g][1] = v.y;
                }
                float2 h = *(const float2*)(ghr + (size_t)r * 512 + hcol);
                hp[nn][half][0] = h.x; hp[nn][half][1] = h.y;
            }
            float acc[2][3][4];
#pragma unroll
            for (int nn = 0; nn < 2; nn++)
                for (int g = 0; g < 3; g++) for (int j = 0; j < 4; j++) acc[nn][g][j] = 0.f;
            rec_gemm<3>(acc, As, Bs, g_hgr[pr], g_Wgr, 1536, 512, 512, b0, colbase, tid, wm, wn, gq, tq);
#pragma unroll
            for (int nn = 0; nn < 2; nn++)
#pragma unroll
            for (int half = 0; half < 2; half++) {
                int ci = half * 2;
                int r = b0 + wm * 16 + gq + half * 8;
                int hcol = colbase + wn * 16 + nn * 8 + 2 * tq;
                size_t si = (size_t)r * 512 + hcol;
                size_t oi = OFF_HS + ((size_t)r * THc + s) * 512 + hcol;
                float hv2[2];
#pragma unroll
                for (int j = 0; j < 2; j++) {
                    float hr = acc[nn][0][ci + j] + bhg[hcol + j];
                    float hz = acc[nn][1][ci + j] + bhg[512 + hcol + j];
                    float hn = acc[nn][2][ci + j] + bhg[1024 + hcol + j];
                    float rv = sigf(xv[nn][half][0][j] + hr);
                    float zv = sigf(xv[nn][half][1][j] + hz);
                    float nv = tanhf(xv[nn][half][2][j] + rv * hn);
                    float hv = (1.f - zv) * nv + zv * hp[nn][half][j];
                    hv2[j] = hv;
                    ghwr[si + j] = to_tf32(hv);
                }
                *(float2*)(ghw + si) = make_float2(hv2[0], hv2[1]);
                *(float2*)(out + oi) = make_float2(hv2[0], hv2[1]);
            }
            chain_bar(2, 64);
        }
    }
}

// ---------------- generic tf32 GEMM 64x128x16 tiles, double-buffered ----------------
template <int EPI, int CAT>
__global__ __launch_bounds__(256) void k_gemm(
    const float* __restrict__ A, const float* __restrict__ Az,
    const float* __restrict__ W, const float* __restrict__ bias,
    float* __restrict__ C, float* __restrict__ Y, int M, int N, int K)
{
    __shared__ float As[2][64 * 20];
    __shared__ float Ws[2][16 * 136];
    const int tid = threadIdx.x, wid = tid >> 5, lane = tid & 31;
    const int gq = lane >> 2, tq = lane & 3;
    const int wm = wid >> 1, wn = wid & 1;
    const int r0 = blockIdx.x * 64, n0 = blockIdx.y * 128;
    const int ar = tid >> 2, aq = tid & 3;
    const int bk = tid >> 5, bc = tid & 31;
    const int ldA = CAT ? 512 : K;

    float acc[8][4];
#pragma unroll
    for (int i = 0; i < 8; i++) for (int q = 0; q < 4; q++) acc[i][q] = 0.f;

    float4 ra, rb0, rb1;
    const int NC = K >> 4;
    auto lda = [&](int kc) {
        int k = kc * 16 + aq * 4;
        const float* p = (CAT && k >= 512) ? (Az + (size_t)(r0 + ar) * 128 + (k - 512))
                                           : (A + (size_t)(r0 + ar) * ldA + k);
        ra = *(const float4*)p;
    };
    auto ldb = [&](int kc) {
        rb0 = *(const float4*)(W + (size_t)(kc * 16 + bk) * N + n0 + bc * 4);
        rb1 = *(const float4*)(W + (size_t)(kc * 16 + bk + 8) * N + n0 + bc * 4);
    };
    auto st = [&](int bf) {
        float* pa = &As[bf][ar * 20 + aq * 4];
        pa[0] = to_tf32(ra.x); pa[1] = to_tf32(ra.y); pa[2] = to_tf32(ra.z); pa[3] = to_tf32(ra.w);
        float* pb = &Ws[bf][bk * 136 + bc * 4];
        pb[0] = to_tf32(rb0.x); pb[1] = to_tf32(rb0.y); pb[2] = to_tf32(rb0.z); pb[3] = to_tf32(rb0.w);
        float* pb2 = &Ws[bf][(bk + 8) * 136 + bc * 4];
        pb2[0] = to_tf32(rb1.x); pb2[1] = to_tf32(rb1.y); pb2[2] = to_tf32(rb1.z); pb2[3] = to_tf32(rb1.w);
    };
    lda(0); ldb(0); st(0); __syncthreads();
    for (int kc = 0; kc < NC; kc++) {
        int cur = kc & 1;
        if (kc + 1 < NC) { lda(kc + 1); ldb(kc + 1); }
#pragma unroll
        for (int kk = 0; kk < 2; kk++) {
            unsigned a[4];
            const int kb = kk * 8, rowb = wm * 16;
            a[0] = fau(As[cur][(rowb + gq) * 20 + kb + tq]);
            a[1] = fau(As[cur][(rowb + gq + 8) * 20 + kb + tq]);
            a[2] = fau(As[cur][(rowb + gq) * 20 + kb + tq + 4]);
            a[3] = fau(As[cur][(rowb + gq + 8) * 20 + kb + tq + 4]);
#pragma unroll
            for (int nf = 0; nf < 8; nf++) {
                const int nb = wn * 64 + nf * 8;
                unsigned bv[2] = { fau(Ws[cur][(kb + tq) * 136 + nb + gq]),
                                   fau(Ws[cur][(kb + tq + 4) * 136 + nb + gq]) };
                mma8(acc[nf], a, bv);
            }
        }
        if (kc + 1 < NC) st(cur ^ 1);
        __syncthreads();
    }
    const int row = r0 + wm * 16 + gq;
    if (EPI == 2) {
        float p0 = 0.f, p1 = 0.f;
#pragma unroll
        for (int nf = 0; nf < 8; nf++) {
            const int colb = n0 + wn * 64 + nf * 8 + 2 * tq;
            const float b0v = bias[colb], b1v = bias[colb + 1];
            float v0 = geluf(acc[nf][0] + b0v), v1 = geluf(acc[nf][1] + b1v);
            float v2 = geluf(acc[nf][2] + b0v), v3 = geluf(acc[nf][3] + b1v);
            p0 += v0 * g_Weh[colb] + v1 * g_Weh[colb + 1];
            p1 += v2 * g_Weh[colb] + v3 * g_Weh[colb + 1];
        }
        p0 += __shfl_xor_sync(0xffffffffu, p0, 1); p0 += __shfl_xor_sync(0xffffffffu, p0, 2);
        p1 += __shfl_xor_sync(0xffffffffu, p1, 1); p1 += __shfl_xor_sync(0xffffffffu, p1, 2);
        if (tq == 0) { atomicAdd(Y + row, p0); atomicAdd(Y + row + 8, p1); }
    } else {
#pragma unroll
        for (int nf = 0; nf < 8; nf++) {
            const int colb = n0 + wn * 64 + nf * 8 + 2 * tq;
            const float b0v = bias[colb], b1v = bias[colb + 1];
            float v0 = acc[nf][0] + b0v, v1 = acc[nf][1] + b1v;
            float v2 = acc[nf][2] + b0v, v3 = acc[nf][3] + b1v;
            if (EPI == 1) { v0 = splus(v0); v1 = splus(v1); v2 = splus(v2); v3 = splus(v3); }
            *(float2*)(C + (size_t)row * N + colb) = make_float2(v0, v1);
            *(float2*)(C + (size_t)(row + 8) * N + colb) = make_float2(v2, v3);
        }
    }
}

// ---------------- reparam sample ----------------
__global__ __launch_bounds__(256) void k_z(const float* __restrict__ out, const float* __restrict__ eps)
{
    int i = blockIdx.x * 256 + threadIdx.x;
    int b = i >> 16, rem = i & 65535;
    int t = rem >> 7, l = rem & 127;
    size_t qi = ((size_t)b * TAc + t) * 128 + l;
    g_z[i] = out[OFF_QM + qi] + out[OFF_QS + qi] * eps[i];
}

// ---------------- host ----------------
extern "C" void kernel_launch(void* const* d_in, const int* in_sizes, int n_in,
                              void* d_out, int out_size)
{
    const float* ph   = (const float*)d_in[0];
    const float* pa   = (const float*)d_in[1];
    const float* eps  = (const float*)d_in[2];
    const float* We   = (const float*)d_in[3];
    const float* be   = (const float*)d_in[4];
    const float* Wihf = (const float*)d_in[5];
    const float* Whhf = (const float*)d_in[6];
    const float* bihf = (const float*)d_in[7];
    const float* bhhf = (const float*)d_in[8];
    const float* Wihb = (const float*)d_in[9];
    const float* Whhb = (const float*)d_in[10];
    const float* bihb = (const float*)d_in[11];
    const float* bhhb = (const float*)d_in[12];
    const float* Wqm  = (const float*)d_in[13];
    const float* bqm  = (const float*)d_in[14];
    const float* Wqs  = (const float*)d_in[15];
    const float* bqs  = (const float*)d_in[16];
    const float* Wihg = (const float*)d_in[17];
    const float* Whhg = (const float*)d_in[18];
    const float* bihg = (const float*)d_in[19];
    const float* bhhg = (const float*)d_in[20];
    const float* Wpm  = (const float*)d_in[21];
    const float* bpm  = (const float*)d_in[22];
    const float* Wps  = (const float*)d_in[23];
    const float* bps  = (const float*)d_in[24];
    const float* We1  = (const float*)d_in[25];
    const float* be1  = (const float*)d_in[26];
    const float* We2  = (const float*)d_in[27];
    const float* be2  = (const float*)d_in[28];
    const float* Whead= (const float*)d_in[29];
    const float* bhead= (const float*)d_in[30];
    float* out = (float*)d_out;

    float *xgf, *xgb, *xgg, *hbi, *zb, *Wf, *Wb, *Wg, *bf, *bb, *bg;
    cudaGetSymbolAddress((void**)&xgf, g_xgf);
    cudaGetSymbolAddress((void**)&xgb, g_xgb);
    cudaGetSymbolAddress((void**)&xgg, g_xgg);
    cudaGetSymbolAddress((void**)&hbi, g_hbi);
    cudaGetSymbolAddress((void**)&zb,  g_z);
    cudaGetSymbolAddress((void**)&Wf,  g_Wf);
    cudaGetSymbolAddress((void**)&Wb,  g_Wb);
    cudaGetSymbolAddress((void**)&Wg,  g_Wg);
    cudaGetSymbolAddress((void**)&bf,  g_bf);
    cudaGetSymbolAddress((void**)&bb,  g_bb);
    cudaGetSymbolAddress((void**)&bg,  g_bg);

    k_fuse<<<256, 256>>>(We, be, Wihf, bihf, Wihb, bihb, Wihg, bihg, We2, be2, Whead, bhead);
    k_round<<<3072, 256>>>(Whhf, Whhb, Whhg);
    k_init<<<512, 256>>>(out);

    // input gates (fused embedding), K=16
    k_xg<<<18432, 256>>>(pa, Wf, bf, xgf, 1024);
    k_xg<<<18432, 256>>>(pa, Wb, bb, xgb, 1024);
    k_xg<<<16384, 256>>>(ph, Wg, bg, xgg, 1536);

    // persistent recurrence, cp.async 3-stage pipelined GEMMs
    const int RSM = (3 * 32 * 20 + 3 * 16 * 264) * 4;
    cudaFuncSetAttribute(k_rec, cudaFuncAttributeMaxDynamicSharedMemorySize, RSM);
    k_rec<<<128, 256, RSM>>>(bhhf, bhhb, bhhg, out);

    // heads
    k_gemm<0, 0><<<dim3(2304, 1), 256>>>(hbi, nullptr, Wqm, bqm, out + OFF_QM, nullptr, BB * TAc, 128, 512);
    k_gemm<1, 0><<<dim3(2304, 1), 256>>>(hbi, nullptr, Wqs, bqs, out + OFF_QS, nullptr, BB * TAc, 128, 512);
    k_gemm<0, 0><<<dim3(2048, 1), 256>>>(out + OFF_HS, nullptr, Wpm, bpm, out + OFF_PM, nullptr, BB * THc, 128, 512);
    k_gemm<1, 0><<<dim3(2048, 1), 256>>>(out + OFF_HS, nullptr, Wps, bps, out + OFF_PS, nullptr, BB * THc, 128, 512);

    // reparam + emission (gelu GEMM fused with folded head dot)
    k_z<<<65536, 256>>>(out, eps);
    k_gemm<2, 1><<<dim3(2048, 4), 256>>>(out + OFF_HS, zb, We1, be1, nullptr, out, BB * THc, 512, 640);
}